// round 3
// baseline (speedup 1.0000x reference)
#include <cuda_runtime.h>

// RSNALoss: pred [128,8192,10] f32, label [128,8192,10] f32, seq_lens [128] i32 -> scalar f32.
//
// Kernel 1: per (batch, block-slice) masked partial sums:
//   acc[0..8]   = sum_l pred[b,l,1..9]            (l < seq_len)
//   acc[9..17]  = sum_l label[b,l,1..9]
//   acc[18]     = sum_l label[b,l,0]
//   acc[19]     = sum_l -(y0*log(p0) + (1-y0)*log(1-p0))
// Written unconditionally to distinct scratch slots -> no atomics, no zero-pass,
// deterministic across graph replays.
//
// Kernel 2: one block, thread b finalizes batch b, block-reduces to the scalar.

#define BATCH 128
#define SEQ   8192
#define CH    10
#define BLOCKS_PER_B 16
#define NTHREADS 256
#define NACC 20

#define IMAGE_WEIGHT 0.0736196319f

__constant__ float c_w[9] = {
    0.0736196319f, 0.09202453988f, 0.1042944785f, 0.1042944785f,
    0.1877300613f, 0.06257668712f, 0.06257668712f, 0.2346625767f,
    0.0782208589f
};

__device__ float g_partials[BATCH * BLOCKS_PER_B * NACC];

__global__ __launch_bounds__(NTHREADS)
void rsna_partial_kernel(const float* __restrict__ pred,
                         const float* __restrict__ label,
                         const int*   __restrict__ seq_lens)
{
    const int b   = blockIdx.y;
    const int blk = blockIdx.x;
    const int tid = threadIdx.x;
    const int sl  = seq_lens[b];

    float acc[NACC];
#pragma unroll
    for (int i = 0; i < NACC; i++) acc[i] = 0.0f;

    // Row base pointers for this batch; each row = 5 float2 (10 floats, 8B aligned).
    const float2* __restrict__ pr = (const float2*)pred  + (size_t)b * SEQ * (CH / 2);
    const float2* __restrict__ lb = (const float2*)label + (size_t)b * SEQ * (CH / 2);

    for (int l = blk * NTHREADS + tid; l < sl; l += BLOCKS_PER_B * NTHREADS) {
        const float2* prow = pr + (size_t)l * 5;
        const float2* lrow = lb + (size_t)l * 5;
        float2 p0 = prow[0], p1 = prow[1], p2 = prow[2], p3 = prow[3], p4 = prow[4];
        float2 l0 = lrow[0], l1 = lrow[1], l2 = lrow[2], l3 = lrow[3], l4 = lrow[4];

        // channels 1..9 of pred
        acc[0] += p0.y; acc[1] += p1.x; acc[2] += p1.y; acc[3] += p2.x;
        acc[4] += p2.y; acc[5] += p3.x; acc[6] += p3.y; acc[7] += p4.x;
        acc[8] += p4.y;
        // channels 1..9 of label
        acc[9]  += l0.y; acc[10] += l1.x; acc[11] += l1.y; acc[12] += l2.x;
        acc[13] += l2.y; acc[14] += l3.x; acc[15] += l3.y; acc[16] += l4.x;
        acc[17] += l4.y;
        // image-level: channel 0
        float p0v = p0.x, y0v = l0.x;
        acc[18] += y0v;
        acc[19] += -(y0v * logf(p0v) + (1.0f - y0v) * logf(1.0f - p0v));
    }

    // warp reduce each accumulator
#pragma unroll
    for (int i = 0; i < NACC; i++) {
#pragma unroll
        for (int off = 16; off > 0; off >>= 1)
            acc[i] += __shfl_xor_sync(0xFFFFFFFFu, acc[i], off);
    }

    __shared__ float smem[(NTHREADS / 32) * NACC];
    const int wid  = tid >> 5;
    const int lane = tid & 31;
    if (lane == 0) {
#pragma unroll
        for (int i = 0; i < NACC; i++) smem[wid * NACC + i] = acc[i];
    }
    __syncthreads();

    // threads 0..19 (all in warp 0) each sum one accumulator over the 8 warps
    if (tid < NACC) {
        float s = 0.0f;
#pragma unroll
        for (int w = 0; w < NTHREADS / 32; w++) s += smem[w * NACC + tid];
        g_partials[((size_t)b * BLOCKS_PER_B + blk) * NACC + tid] = s;
    }
}

__global__ __launch_bounds__(BATCH)
void rsna_final_kernel(const int* __restrict__ seq_lens,
                       float* __restrict__ out)
{
    const int b = threadIdx.x;  // 128 threads, one per batch

    float acc[NACC];
#pragma unroll
    for (int i = 0; i < NACC; i++) acc[i] = 0.0f;

    const float* base = &g_partials[(size_t)b * BLOCKS_PER_B * NACC];
#pragma unroll
    for (int blk = 0; blk < BLOCKS_PER_B; blk++) {
#pragma unroll
        for (int i = 0; i < NACC; i++) acc[i] += base[blk * NACC + i];
    }

    const float len = (float)seq_lens[b];
    const float inv = 1.0f / len;

    float exam = 0.0f;
#pragma unroll
    for (int c = 0; c < 9; c++) {
        float pm = acc[c]     * inv;
        float ym = acc[9 + c] * inv;
        exam += c_w[c] * (-(ym * logf(pm) + (1.0f - ym) * logf(1.0f - pm)));
    }

    float y0m  = acc[18] * inv;
    float iw   = IMAGE_WEIGHT * y0m;
    float num  = exam + acc[19] * iw;   // exam_loss_b + image_loss_b
    float wsum = iw * len;              // img_w * len contribution

    // block reduce (4 warps of 32)
#pragma unroll
    for (int off = 16; off > 0; off >>= 1) {
        num  += __shfl_xor_sync(0xFFFFFFFFu, num,  off);
        wsum += __shfl_xor_sync(0xFFFFFFFFu, wsum, off);
    }
    __shared__ float s_num[4], s_ws[4];
    const int wid  = b >> 5;
    const int lane = b & 31;
    if (lane == 0) { s_num[wid] = num; s_ws[wid] = wsum; }
    __syncthreads();
    if (b == 0) {
        float n = 0.0f, w = 0.0f;
#pragma unroll
        for (int i = 0; i < 4; i++) { n += s_num[i]; w += s_ws[i]; }
        float sumw = 0.0f;
#pragma unroll
        for (int c = 0; c < 9; c++) sumw += c_w[c];
        out[0] = n / ((float)BATCH * sumw + w);
    }
}

extern "C" void kernel_launch(void* const* d_in, const int* in_sizes, int n_in,
                              void* d_out, int out_size)
{
    const float* pred  = (const float*)d_in[0];
    const float* label = (const float*)d_in[1];
    const int*   slens = (const int*)d_in[2];
    float* out = (float*)d_out;

    dim3 grid(BLOCKS_PER_B, BATCH);
    rsna_partial_kernel<<<grid, NTHREADS>>>(pred, label, slens);
    rsna_final_kernel<<<1, BATCH>>>(slens, out);
}

// round 4
// speedup vs baseline: 1.8567x; 1.8567x over previous
#include <cuda_runtime.h>

// RSNALoss fused single-kernel:
//  Phase 1 (all 1024 blocks): masked partial sums per (batch, block-slice).
//    acc[0..8]  = sum pred[b,l,1..9]   (l < seq_len)
//    acc[9..17] = sum label[b,l,1..9]
//    acc[18]    = sum label[b,l,0]
//    acc[19]    = sum -(y0*log(p0)+(1-y0)*log(1-p0))
//  Partials stored accumulator-major -> coalesced float4 reads in phase 2.
//  Phase 2 (atomic-ticket last block): thread b finalizes batch b, block-reduces
//  to the scalar. Deterministic: ticket order only picks WHICH block finalizes;
//  the reduction reads the complete, fixed partial array.

#define BATCH 128
#define SEQ   8192
#define NTHREADS 256
#define RPT   4
#define BPB   8                      // 8 * 256 * 4 = 8192 rows covered per batch
#define NBLK  (BATCH * BPB)          // 1024 blocks
#define NACC  20
#define NWARP (NTHREADS / 32)

#define IMAGE_WEIGHT 0.0736196319f

__constant__ float c_w[9] = {
    0.0736196319f, 0.09202453988f, 0.1042944785f, 0.1042944785f,
    0.1877300613f, 0.06257668712f, 0.06257668712f, 0.2346625767f,
    0.0782208589f
};

__device__ float g_partials[NACC * NBLK];   // [acc][block]  (accumulator-major)
__device__ unsigned int g_ticket;           // zero-init; reset by last block

__global__ __launch_bounds__(NTHREADS)
void rsna_fused_kernel(const float* __restrict__ pred,
                       const float* __restrict__ label,
                       const int*   __restrict__ seq_lens,
                       float* __restrict__ out)
{
    const int b   = blockIdx.y;
    const int blk = blockIdx.x;
    const int tid = threadIdx.x;
    const int sl  = __ldg(&seq_lens[b]);

    float acc[NACC];
#pragma unroll
    for (int i = 0; i < NACC; i++) acc[i] = 0.0f;

    // Rows are 10 floats (40B, 8B-aligned) -> 5 x float2 per row.
    const float2* __restrict__ pr = (const float2*)pred  + (size_t)b * SEQ * 5;
    const float2* __restrict__ lb = (const float2*)label + (size_t)b * SEQ * 5;

    // ---- Phase 1: batch 4 rows per thread, all loads independent (MLP ~40) ----
    float2 pv[RPT][5], lv[RPT][5];
    bool ok[RPT];
    const int base = blk * (NTHREADS * RPT) + tid;
#pragma unroll
    for (int r = 0; r < RPT; r++) {
        const int l = base + r * NTHREADS;
        ok[r] = (l < sl);
#pragma unroll
        for (int j = 0; j < 5; j++) {
            pv[r][j] = make_float2(0.0f, 0.0f);
            lv[r][j] = make_float2(0.0f, 0.0f);
        }
        pv[r][0].x = 0.5f;   // dummy p0 keeps the (masked) BCE finite
        if (ok[r]) {
            const float2* prow = pr + (size_t)l * 5;
            const float2* lrow = lb + (size_t)l * 5;
#pragma unroll
            for (int j = 0; j < 5; j++) { pv[r][j] = prow[j]; lv[r][j] = lrow[j]; }
        }
    }

#pragma unroll
    for (int r = 0; r < RPT; r++) {
        acc[0] += pv[r][0].y; acc[1] += pv[r][1].x; acc[2] += pv[r][1].y;
        acc[3] += pv[r][2].x; acc[4] += pv[r][2].y; acc[5] += pv[r][3].x;
        acc[6] += pv[r][3].y; acc[7] += pv[r][4].x; acc[8] += pv[r][4].y;

        acc[9]  += lv[r][0].y; acc[10] += lv[r][1].x; acc[11] += lv[r][1].y;
        acc[12] += lv[r][2].x; acc[13] += lv[r][2].y; acc[14] += lv[r][3].x;
        acc[15] += lv[r][3].y; acc[16] += lv[r][4].x; acc[17] += lv[r][4].y;

        const float p0v = pv[r][0].x;
        const float y0v = lv[r][0].x;
        acc[18] += y0v;
        const float bce = -(y0v * __logf(p0v) + (1.0f - y0v) * __logf(1.0f - p0v));
        acc[19] += ok[r] ? bce : 0.0f;
    }

    // ---- warp + block reduce the 20 accumulators ----
#pragma unroll
    for (int i = 0; i < NACC; i++) {
#pragma unroll
        for (int off = 16; off > 0; off >>= 1)
            acc[i] += __shfl_xor_sync(0xFFFFFFFFu, acc[i], off);
    }

    __shared__ float s_red[NWARP * NACC];
    const int wid  = tid >> 5;
    const int lane = tid & 31;
    if (lane == 0) {
#pragma unroll
        for (int i = 0; i < NACC; i++) s_red[wid * NACC + i] = acc[i];
    }
    __syncthreads();

    if (tid < NACC) {
        float s = 0.0f;
#pragma unroll
        for (int w = 0; w < NWARP; w++) s += s_red[w * NACC + tid];
        // accumulator-major: [acc][b*BPB + blk]
        g_partials[tid * NBLK + b * BPB + blk] = s;
    }

    // ---- ticket: last finished block finalizes ----
    __shared__ int s_last;
    __threadfence();
    __syncthreads();
    if (tid == 0) {
        unsigned int t = atomicAdd(&g_ticket, 1u);
        s_last = (t == (unsigned int)(NBLK - 1)) ? 1 : 0;
    }
    __syncthreads();
    if (!s_last) return;

    if (tid == 0) g_ticket = 0;   // reset for next (graph-replayed) launch
    __threadfence();

    // ---- Phase 2: thread b (<128) finalizes batch b; coalesced float4 loads ----
    float num = 0.0f, wsum = 0.0f;
    if (tid < BATCH) {
        const float4* gp = (const float4*)g_partials;
        float a[NACC];
#pragma unroll
        for (int i = 0; i < NACC; i++) {
            // 8 contiguous floats per (acc, batch): 2 x float4
            float4 x = gp[i * (NBLK / 4) + tid * 2];
            float4 y = gp[i * (NBLK / 4) + tid * 2 + 1];
            a[i] = ((x.x + x.y) + (x.z + x.w)) + ((y.x + y.y) + (y.z + y.w));
        }

        const float len = (float)__ldg(&seq_lens[tid]);
        const float inv = 1.0f / len;

        float exam = 0.0f;
#pragma unroll
        for (int c = 0; c < 9; c++) {
            const float pm = a[c]     * inv;
            const float ym = a[9 + c] * inv;
            exam += c_w[c] * (-(ym * __logf(pm) + (1.0f - ym) * __logf(1.0f - pm)));
        }

        const float y0m = a[18] * inv;
        const float iw  = IMAGE_WEIGHT * y0m;
        num  = exam + a[19] * iw;
        wsum = iw * len;
    }

    // block reduce num/wsum over all NTHREADS (inactive threads hold 0)
#pragma unroll
    for (int off = 16; off > 0; off >>= 1) {
        num  += __shfl_xor_sync(0xFFFFFFFFu, num,  off);
        wsum += __shfl_xor_sync(0xFFFFFFFFu, wsum, off);
    }
    __shared__ float s_num[NWARP], s_ws[NWARP];
    if (lane == 0) { s_num[wid] = num; s_ws[wid] = wsum; }
    __syncthreads();
    if (tid == 0) {
        float n = 0.0f, w = 0.0f;
#pragma unroll
        for (int i = 0; i < NWARP; i++) { n += s_num[i]; w += s_ws[i]; }
        float sumw = 0.0f;
#pragma unroll
        for (int c = 0; c < 9; c++) sumw += c_w[c];
        out[0] = n / ((float)BATCH * sumw + w);
    }
}

extern "C" void kernel_launch(void* const* d_in, const int* in_sizes, int n_in,
                              void* d_out, int out_size)
{
    const float* pred  = (const float*)d_in[0];
    const float* label = (const float*)d_in[1];
    const int*   slens = (const int*)d_in[2];
    float* out = (float*)d_out;

    dim3 grid(BPB, BATCH);
    rsna_fused_kernel<<<grid, NTHREADS>>>(pred, label, slens, out);
}

// round 6
// speedup vs baseline: 2.1334x; 1.1490x over previous
#include <cuda_runtime.h>
#include <cstdint>

// RSNALoss fused, smem-staged:
//  Phase 1: each block owns a 1024-row tile of one batch. Chunks of 256 rows are
//  cp.async'd (fully coalesced float4 stream, zero wavefront replay) into a
//  double-buffered SMEM stage; each thread then consumes one row from SMEM.
//  Phase 2: atomic-ticket last block finalizes (order-independent -> deterministic).

#define BATCH 128
#define SEQ   8192
#define NT    256
#define CHUNK 256                       // rows per chunk (== NT: 1 row/thread)
#define CH10  (CHUNK * 10)              // floats per tensor per chunk (2560)
#define F4PT  (CH10 / 4)                // float4 per tensor per chunk (640)
#define TILE_CHUNKS 4
#define TILE_ROWS   (CHUNK * TILE_CHUNKS)   // 1024
#define BPB   (SEQ / TILE_ROWS)         // 8 tiles per batch
#define NBLK  (BATCH * BPB)             // 1024 blocks
#define NACC  20
#define NWARP (NT / 32)

#define IMAGE_WEIGHT 0.0736196319f

__constant__ float c_w[9] = {
    0.0736196319f, 0.09202453988f, 0.1042944785f, 0.1042944785f,
    0.1877300613f, 0.06257668712f, 0.06257668712f, 0.2346625767f,
    0.0782208589f
};

__device__ __align__(16) float g_partials[NACC * NBLK];  // [acc][block]
__device__ unsigned int g_ticket;                        // zero-init; reset by last block

__device__ __forceinline__ void cp16(uint32_t s, const void* g, bool p)
{
    asm volatile(
        "{ .reg .pred q; setp.ne.u32 q, %2, 0;"
        "  @q cp.async.cg.shared.global [%0], [%1], 16; }"
        :: "r"(s), "l"(g), "r"((int)p));
}

__global__ __launch_bounds__(NT)
void rsna_fused_kernel(const float* __restrict__ pred,
                       const float* __restrict__ label,
                       const int*   __restrict__ seq_lens,
                       float* __restrict__ out)
{
    const int b    = blockIdx.y;
    const int tile = blockIdx.x;
    const int tid  = threadIdx.x;
    const int sl   = __ldg(&seq_lens[b]);

    __shared__ __align__(16) float s_pred[2][CH10];
    __shared__ __align__(16) float s_lab [2][CH10];

    float acc[NACC];
#pragma unroll
    for (int i = 0; i < NACC; i++) acc[i] = 0.0f;

    const int tile_base = tile * TILE_ROWS;
    int nch = 0;
    {
        const int rem = sl - tile_base;
        if (rem > 0) nch = min(TILE_CHUNKS, (rem + CHUNK - 1) / CHUNK);
    }

    const float* pbase = pred  + (size_t)b * SEQ * 10;
    const float* lbase = label + (size_t)b * SEQ * 10;

    // ---- prefetch helper (manually inlined via macro-ish lambda) ----
    auto prefetch = [&](int c, int buf) {
        const int cb  = tile_base + c * CHUNK;
        const int lim = (sl - cb) * 10;     // floats needed in this chunk
        const float4* pg = (const float4*)(pbase + (size_t)cb * 10);
        const float4* lg = (const float4*)(lbase + (size_t)cb * 10);
        const uint32_t sp = (uint32_t)__cvta_generic_to_shared(&s_pred[buf][0]);
        const uint32_t sy = (uint32_t)__cvta_generic_to_shared(&s_lab [buf][0]);
#pragma unroll
        for (int j = 0; j < 5; j++) {       // 1280 float4 over 256 threads
            const int idx = tid + j * NT;
            if (idx < F4PT) {
                cp16(sp + idx * 16, pg + idx, (idx * 4) < lim);
            } else {
                const int i2 = idx - F4PT;
                cp16(sy + i2 * 16, lg + i2, (i2 * 4) < lim);
            }
        }
        asm volatile("cp.async.commit_group;");
    };

    if (nch > 0) prefetch(0, 0);

    for (int c = 0; c < nch; c++) {
        if (c + 1 < nch) {
            prefetch(c + 1, (c + 1) & 1);
            asm volatile("cp.async.wait_group 1;");
        } else {
            asm volatile("cp.async.wait_group 0;");
        }
        __syncthreads();

        const int row = tile_base + c * CHUNK + tid;
        if (row < sl) {
            const float2* pr = (const float2*)&s_pred[c & 1][tid * 10];
            const float2* lr = (const float2*)&s_lab [c & 1][tid * 10];
            float2 p0 = pr[0], p1 = pr[1], p2 = pr[2], p3 = pr[3], p4 = pr[4];
            float2 l0 = lr[0], l1 = lr[1], l2 = lr[2], l3 = lr[3], l4 = lr[4];

            acc[0] += p0.y; acc[1] += p1.x; acc[2] += p1.y; acc[3] += p2.x;
            acc[4] += p2.y; acc[5] += p3.x; acc[6] += p3.y; acc[7] += p4.x;
            acc[8] += p4.y;

            acc[9]  += l0.y; acc[10] += l1.x; acc[11] += l1.y; acc[12] += l2.x;
            acc[13] += l2.y; acc[14] += l3.x; acc[15] += l3.y; acc[16] += l4.x;
            acc[17] += l4.y;

            const float p0v = p0.x, y0v = l0.x;
            acc[18] += y0v;
            acc[19] += -(y0v * __logf(p0v) + (1.0f - y0v) * __logf(1.0f - p0v));
        }
        __syncthreads();   // buffer (c&1) may be overwritten by prefetch(c+2)
    }

    // ---- warp + block reduce the 20 accumulators ----
#pragma unroll
    for (int i = 0; i < NACC; i++) {
#pragma unroll
        for (int off = 16; off > 0; off >>= 1)
            acc[i] += __shfl_xor_sync(0xFFFFFFFFu, acc[i], off);
    }

    __shared__ float s_red[NWARP * NACC];
    const int wid  = tid >> 5;
    const int lane = tid & 31;
    if (lane == 0) {
#pragma unroll
        for (int i = 0; i < NACC; i++) s_red[wid * NACC + i] = acc[i];
    }
    __syncthreads();

    if (tid < NACC) {
        float s = 0.0f;
#pragma unroll
        for (int w = 0; w < NWARP; w++) s += s_red[w * NACC + tid];
        g_partials[tid * NBLK + b * BPB + tile] = s;   // accumulator-major
    }

    // ---- ticket: last finished block finalizes ----
    __shared__ int s_last;
    __threadfence();
    __syncthreads();
    if (tid == 0) {
        unsigned int t = atomicAdd(&g_ticket, 1u);
        s_last = (t == (unsigned int)(NBLK - 1)) ? 1 : 0;
    }
    __syncthreads();
    if (!s_last) return;

    if (tid == 0) g_ticket = 0;
    __threadfence();

    // ---- Phase 2: thread b finalizes batch b; coalesced float4 over L2-hot partials ----
    float num = 0.0f, wsum = 0.0f;
    if (tid < BATCH) {
        const float4* gp = (const float4*)g_partials;
        float a[NACC];
#pragma unroll
        for (int i = 0; i < NACC; i++) {
            float4 x = gp[i * (NBLK / 4) + tid * 2];
            float4 y = gp[i * (NBLK / 4) + tid * 2 + 1];
            a[i] = ((x.x + x.y) + (x.z + x.w)) + ((y.x + y.y) + (y.z + y.w));
        }

        const float len = (float)__ldg(&seq_lens[tid]);
        const float inv = 1.0f / len;

        float exam = 0.0f;
#pragma unroll
        for (int c = 0; c < 9; c++) {
            const float pm = a[c]     * inv;
            const float ym = a[9 + c] * inv;
            exam += c_w[c] * (-(ym * __logf(pm) + (1.0f - ym) * __logf(1.0f - pm)));
        }

        const float y0m = a[18] * inv;
        const float iw  = IMAGE_WEIGHT * y0m;
        num  = exam + a[19] * iw;
        wsum = iw * len;
    }

#pragma unroll
    for (int off = 16; off > 0; off >>= 1) {
        num  += __shfl_xor_sync(0xFFFFFFFFu, num,  off);
        wsum += __shfl_xor_sync(0xFFFFFFFFu, wsum, off);
    }
    __shared__ float s_num[NWARP], s_ws[NWARP];
    if (lane == 0) { s_num[wid] = num; s_ws[wid] = wsum; }
    __syncthreads();
    if (tid == 0) {
        float n = 0.0f, w = 0.0f;
#pragma unroll
        for (int i = 0; i < NWARP; i++) { n += s_num[i]; w += s_ws[i]; }
        float sumw = 0.0f;
#pragma unroll
        for (int c = 0; c < 9; c++) sumw += c_w[c];
        out[0] = n / ((float)BATCH * sumw + w);
    }
}

extern "C" void kernel_launch(void* const* d_in, const int* in_sizes, int n_in,
                              void* d_out, int out_size)
{
    const float* pred  = (const float*)d_in[0];
    const float* label = (const float*)d_in[1];
    const int*   slens = (const int*)d_in[2];
    float* out = (float*)d_out;

    dim3 grid(BPB, BATCH);
    rsna_fused_kernel<<<grid, NT>>>(pred, label, slens, out);
}